// round 13
// baseline (speedup 1.0000x reference)
#include <cuda_runtime.h>
#include <math.h>

namespace {
constexpr int B_ = 32, L_ = 32, D_ = 512, H_ = 512;
constexpr int H2_ = 1024, H5_ = 2560;
constexpr int PSLOT = 64, ZSLOT = 63;   // pool slots per batch; 63 = zero slot
constexpr int CSLOT = 96, DSLOT = 95;   // cache slots per batch; 95 = dummy
constexpr int NCTA = 160;               // persistent grid (80 n-tiles x 2 k-chunks)
}

typedef unsigned long long u64;

__device__ __align__(16) float g_poolH[B_ * PSLOT * H_];
__device__ __align__(16) float g_poolC[B_ * PSLOT * H_];
__device__ __align__(16) float g_uL[B_ * PSLOT * H5_];
__device__ __align__(16) float g_uR[B_ * PSLOT * H5_];
__device__ __align__(16) float g_uLp[B_ * PSLOT * H5_];  // K-chunk-1 partials
__device__ __align__(16) float g_uRp[B_ * PSLOT * H5_];
__device__ __align__(16) float g_cacheH[B_ * CSLOT * H_];
__device__ __align__(16) float g_cacheC[B_ * CSLOT * H_];
__device__ float g_logit[B_ * CSLOT];
__device__ int4  g_tasks[2 * B_];
__device__ int   g_newSlot[B_];
__device__ int   g_slotOf[B_ * L_];
__device__ int   g_cidx[B_ * L_];
__device__ int2  g_mlist[1024];
__device__ int   g_mcount;
__device__ unsigned g_barCnt[64];

__device__ __forceinline__ float sigm(float x) { return 1.f / (1.f + expf(-x)); }

#define FFMA2(d, a, b) asm("fma.rn.f32x2 %0, %1, %2, %0;" : "+l"(d) : "l"(a), "l"(b))
__device__ __forceinline__ u64 pk2(float lo, float hi) {
    u64 r; asm("mov.b64 %0, {%1, %2};" : "=l"(r) : "f"(lo), "f"(hi)); return r;
}
__device__ __forceinline__ float2 up2(u64 p) {
    float2 r; asm("mov.b64 {%0, %1}, %2;" : "=f"(r.x), "=f"(r.y) : "l"(p)); return r;
}

__device__ __forceinline__ void gridBar(int id) {
    __syncthreads();
    if (threadIdx.x == 0) {
        __threadfence();
        atomicAdd(&g_barCnt[id], 1u);
        while (*(volatile unsigned*)&g_barCnt[id] < (unsigned)NCTA) {}
        __threadfence();
    }
    __syncthreads();
}

// ---------------------------------------------------------------------------
__global__ void kInit(const int* __restrict__ len) {
    int t = blockIdx.x * blockDim.x + threadIdx.x;
    int nthr = gridDim.x * blockDim.x;   // 16384
    if (t < 64) g_barCnt[t] = 0u;
    if (t < B_ * L_) {
        int p = t % L_;
        g_slotOf[t] = p;
        g_cidx[t]   = (p < L_ - 1) ? p : DSLOT;
    }
    if (t < B_) g_logit[t * CSLOT + DSLOT] = 0.f;
    if (blockIdx.x == 0 && threadIdx.x < B_) {
        int b = threadIdx.x, off = 0;
        for (int j = 0; j < b; j++) {
            int c = len[j] + 1; if (c > 32) c = 32; off += c;
        }
        int c = len[b] + 1; if (c > 32) c = 32;
        for (int j = 0; j < c; j++) g_mlist[off + j] = make_int2(b, j);
        if (b == B_ - 1) g_mcount = off + c;
    }
    for (int i = t; i < B_ * H_; i += nthr) {
        int b = i / H_, j = i % H_;
        g_poolH[(b * PSLOT + ZSLOT) * H_ + j] = 0.f;
        g_poolC[(b * PSLOT + ZSLOT) * H_ + j] = 0.f;
        g_cacheH[(b * CSLOT + DSLOT) * H_ + j] = 0.f;
        g_cacheC[(b * CSLOT + DSLOT) * H_ + j] = 0.f;
    }
    for (int i = t; i < B_ * H5_; i += nthr) {
        int b = i / H5_, j = i % H5_;
        g_uL[(b * PSLOT + ZSLOT) * H5_ + j] = 0.f;
        g_uR[(b * PSLOT + ZSLOT) * H5_ + j] = 0.f;
    }
    // zero the partial buffers entirely (leaf slots must read +0)
    {
        float4 z = make_float4(0.f, 0.f, 0.f, 0.f);
        int total = B_ * PSLOT * H5_ / 4;
        for (int i = t; i < total; i += nthr) {
            ((float4*)g_uLp)[i] = z;
            ((float4*)g_uRp)[i] = z;
        }
    }
}

// ---------------------------------------------------------------------------
// 32x128 GEMM core, 128 threads, 4 rows x 8 cols per thread (f32x2 packed).
// ---------------------------------------------------------------------------
__device__ __forceinline__ void gemm32core(const float* aPtr, const float* bPtr,
                                           int ldb, int K, int tid,
                                           float (*Xs)[44], float (*Ws)[132],
                                           u64 (*acc)[4]) {
    const int ar = tid >> 2, aq = (tid & 3) * 4;
    const int wr = tid >> 3, wj = tid & 7;
    const int ty = tid >> 4, tx = tid & 15;
    float4 xa  = *(const float4*)(aPtr);
    float4 wv0 = *(const float4*)(bPtr);
    float4 wv1 = *(const float4*)(bPtr + 32);
    float4 wv2 = *(const float4*)(bPtr + 64);
    float4 wv3 = *(const float4*)(bPtr + 96);
    for (int k0 = 0; k0 < K; k0 += 16) {
        Xs[aq+0][ar] = xa.x; Xs[aq+1][ar] = xa.y;
        Xs[aq+2][ar] = xa.z; Xs[aq+3][ar] = xa.w;
        *(float4*)&Ws[wr][wj*4     ] = wv0;
        *(float4*)&Ws[wr][wj*4 + 32] = wv1;
        *(float4*)&Ws[wr][wj*4 + 64] = wv2;
        *(float4*)&Ws[wr][wj*4 + 96] = wv3;
        __syncthreads();
        if (k0 + 16 < K) {
            xa = *(const float4*)(aPtr + k0 + 16);
            const float* bn = bPtr + (k0 + 16) * ldb;
            wv0 = *(const float4*)(bn);
            wv1 = *(const float4*)(bn + 32);
            wv2 = *(const float4*)(bn + 64);
            wv3 = *(const float4*)(bn + 96);
        }
#pragma unroll
        for (int kk = 0; kk < 16; kk++) {
            float4 a = *(const float4*)&Xs[kk][ty*4];
            u64 pa0 = pk2(a.x,a.x), pa1 = pk2(a.y,a.y);
            u64 pa2 = pk2(a.z,a.z), pa3 = pk2(a.w,a.w);
            u64 bb0 = *(const u64*)&Ws[kk][tx*2];
            u64 bb1 = *(const u64*)&Ws[kk][32 + tx*2];
            u64 bb2 = *(const u64*)&Ws[kk][64 + tx*2];
            u64 bb3 = *(const u64*)&Ws[kk][96 + tx*2];
            FFMA2(acc[0][0],pa0,bb0); FFMA2(acc[0][1],pa0,bb1); FFMA2(acc[0][2],pa0,bb2); FFMA2(acc[0][3],pa0,bb3);
            FFMA2(acc[1][0],pa1,bb0); FFMA2(acc[1][1],pa1,bb1); FFMA2(acc[1][2],pa1,bb2); FFMA2(acc[1][3],pa1,bb3);
            FFMA2(acc[2][0],pa2,bb0); FFMA2(acc[2][1],pa2,bb1); FFMA2(acc[2][2],pa2,bb2); FFMA2(acc[2][3],pa2,bb3);
            FFMA2(acc[3][0],pa3,bb0); FFMA2(acc[3][1],pa3,bb1); FFMA2(acc[3][2],pa3,bb2); FFMA2(acc[3][3],pa3,bb3);
        }
        __syncthreads();
    }
}

// ---------------------------------------------------------------------------
// Leaf GEMM: hc = inp @ W_word + b_word. M=1024, N=1024, K=512. grid(32,8).
// ---------------------------------------------------------------------------
__global__ void __launch_bounds__(128) kLeafGemm(const float* __restrict__ inp,
                                                 const float* __restrict__ Ww,
                                                 const float* __restrict__ bw,
                                                 float* __restrict__ nodes) {
    const int m0 = blockIdx.x * 32, n0 = blockIdx.y * 128;
    __shared__ __align__(16) float Xs[16][44];
    __shared__ __align__(16) float Ws[16][132];
    const int tid = threadIdx.x;
    u64 acc[4][4] = {};
    const float* aPtr = inp + (m0 + (tid >> 2)) * D_ + (tid & 3) * 4;
    const float* bPtr = Ww + (tid >> 3) * H2_ + n0 + (tid & 7) * 4;
    gemm32core(aPtr, bPtr, H2_, D_, tid, Xs, Ws, acc);

    const int ty = tid >> 4, tx = tid & 15;
    const int cHalf = (n0 >= H_) ? 1 : 0;
#pragma unroll
    for (int r = 0; r < 4; r++) {
        int m = m0 + ty * 4 + r, b = m / L_, l = m % L_;
#pragma unroll
        for (int p = 0; p < 4; p++) {
            int n = n0 + 32 * p + tx * 2;
            float2 bias = *(const float2*)(bw + n);
            float2 v = up2(acc[r][p]);
            v.x += bias.x; v.y += bias.y;
            if (!cHalf) {
                *(float2*)&g_poolH[(b * PSLOT + l) * H_ + n] = v;
                *(float2*)&nodes[(b * 63 + l) * H_ + n] = v;
            } else {
                *(float2*)&g_poolC[(b * PSLOT + l) * H_ + (n - H_)] = v;
            }
        }
    }
}

// ---------------------------------------------------------------------------
// Compacted front u-GEMM, both halves: grid(32, 40); y<20 -> uL, else uR.
// ---------------------------------------------------------------------------
__global__ void __launch_bounds__(128) kUGemm0(const float* __restrict__ Wc) {
    const int cnt = g_mcount;
    const int m0 = blockIdx.x * 32;
    if (m0 >= cnt) return;
    const int half = (blockIdx.y >= 20) ? 1 : 0;
    const int nn = (blockIdx.y - half * 20) * 128;
    __shared__ __align__(16) float Xs[16][44];
    __shared__ __align__(16) float Ws[16][132];
    __shared__ int2 sRows[32];
    const int tid = threadIdx.x;
    if (tid < 32) {
        int r = m0 + tid; if (r >= cnt) r = cnt - 1;
        sRows[tid] = g_mlist[r];
    }
    __syncthreads();
    u64 acc[4][4] = {};
    int2 me = sRows[tid >> 2];
    const float* aPtr = g_poolH + (me.x * PSLOT + me.y) * H_ + (tid & 3) * 4;
    const float* bPtr = Wc + (half * H_ + (tid >> 3)) * H5_ + nn + (tid & 7) * 4;
    gemm32core(aPtr, bPtr, H5_, H_, tid, Xs, Ws, acc);

    const int ty = tid >> 4, tx = tid & 15;
    float* U = half ? g_uR : g_uL;
#pragma unroll
    for (int r = 0; r < 4; r++) {
        int row = m0 + ty * 4 + r;
        if (row < cnt) {
            int2 e = sRows[ty * 4 + r];
            float* dst = U + (e.x * PSLOT + e.y) * H5_ + nn;
#pragma unroll
            for (int p = 0; p < 4; p++)
                *(float2*)&dst[32 * p + tx * 2] = up2(acc[r][p]);
        }
    }
}

// ---------------------------------------------------------------------------
// Dual-buffer pair activation: u = primary + partial (partial is 0 for leaves).
// lt in [0,128), each thread does 4 elements.
// ---------------------------------------------------------------------------
__device__ __forceinline__ void actPair4D(int b, int ls, int rs, int cs,
                                          const float* __restrict__ bc,
                                          const float* __restrict__ q,
                                          int lt, float* red) {
    const float* ul  = g_uL  + (b * PSLOT + ls) * H5_;
    const float* ulp = g_uLp + (b * PSLOT + ls) * H5_;
    const float* ur  = g_uR  + (b * PSLOT + rs) * H5_;
    const float* urp = g_uRp + (b * PSLOT + rs) * H5_;
    const float* cl = g_poolC + (b * PSLOT + ls) * H_;
    const float* cr = g_poolC + (b * PSLOT + rs) * H_;
    float* oh = g_cacheH + (b * CSLOT + cs) * H_;
    float* oc = g_cacheC + (b * CSLOT + cs) * H_;
    int j = lt * 4;
    float G[5][4];
#pragma unroll
    for (int g = 0; g < 5; g++) {
        float4 a  = *(const float4*)(ul  + g * H_ + j);
        float4 ap = *(const float4*)(ulp + g * H_ + j);
        float4 r  = *(const float4*)(ur  + g * H_ + j);
        float4 rp = *(const float4*)(urp + g * H_ + j);
        float4 c  = *(const float4*)(bc + g * H_ + j);
        G[g][0] = (a.x + ap.x) + (r.x + rp.x) + c.x;
        G[g][1] = (a.y + ap.y) + (r.y + rp.y) + c.y;
        G[g][2] = (a.z + ap.z) + (r.z + rp.z) + c.z;
        G[g][3] = (a.w + ap.w) + (r.w + rp.w) + c.w;
    }
    float4 cl4 = *(const float4*)(cl + j);
    float4 cr4 = *(const float4*)(cr + j);
    float4 q4  = *(const float4*)(q + j);
    float clv[4] = {cl4.x, cl4.y, cl4.z, cl4.w};
    float crv[4] = {cr4.x, cr4.y, cr4.z, cr4.w};
    float hv[4], cv[4];
#pragma unroll
    for (int l = 0; l < 4; l++) {
        float c = clv[l] * sigm(G[1][l] + 1.f) + crv[l] * sigm(G[2][l] + 1.f)
                + tanhf(G[3][l]) * sigm(G[0][l]);
        hv[l] = sigm(G[4][l]) * tanhf(c); cv[l] = c;
    }
    *(float4*)(oh + j) = make_float4(hv[0], hv[1], hv[2], hv[3]);
    *(float4*)(oc + j) = make_float4(cv[0], cv[1], cv[2], cv[3]);
    float acc = hv[0]*q4.x + hv[1]*q4.y + hv[2]*q4.z + hv[3]*q4.w;
    for (int o = 16; o > 0; o >>= 1) acc += __shfl_down_sync(0xffffffffu, acc, o);
    if ((lt & 31) == 0) red[lt >> 5] = acc;
    __syncthreads();
    if (lt == 0)
        g_logit[b * CSLOT + cs] = red[0] + red[1] + red[2] + red[3];
}

// ---------------------------------------------------------------------------
// Select for batch b at step stepI (direct-store partials: no zeroing).
// ---------------------------------------------------------------------------
__device__ void doSelect(int b, int stepI, const int* __restrict__ len,
                         float* __restrict__ nodes, float* __restrict__ hf,
                         float* __restrict__ cf,
                         int* sPos, int* sPair, int* sKp) {
    int t = threadIdx.x;
    if (t < 32) sPos[t] = g_slotOf[b * L_ + t];
    if (t < 31) sPair[t] = g_cidx[b * L_ + t];
    __syncthreads();
    int lb = len[b];
    if (stepI < lb - 1) {
        if (t == 0) {
            int cand = lb - 1 - stepI, k = 0;
            float best = -1e30f;
            for (int j = 0; j < cand; j++) {
                float v = g_logit[b * CSLOT + sPair[j]];
                if (v > best) { best = v; k = j; }
            }
            *sKp = k;
        }
        __syncthreads();
        int k = *sKp, cs = sPair[k], mslot = 32 + stepI;
        const float* ch = &g_cacheH[(b * CSLOT + cs) * H_];
        const float* cc = &g_cacheC[(b * CSLOT + cs) * H_];
        float* ph = &g_poolH[(b * PSLOT + mslot) * H_];
        float* pc = &g_poolC[(b * PSLOT + mslot) * H_];
        float* nd = &nodes[(b * 63 + 32 + stepI) * H_];
        for (int j = t; j < H_; j += blockDim.x) {
            float hvv = ch[j], cvv = cc[j];
            ph[j] = hvv; pc[j] = cvv; nd[j] = hvv;
            if (stepI == L_ - 2) { hf[b * H_ + j] = hvv; cf[b * H_ + j] = cvv; }
        }
        if (t < 32) {
            int np = (t < k) ? sPos[t] : (t == k) ? mslot : (t < 31) ? sPos[t + 1] : ZSLOT;
            g_slotOf[b * L_ + t] = np;
        }
        if (t < 31) {
            int np;
            if      (t <  k - 1) np = sPair[t];
            else if (t == k - 1) np = 31 + 2 * stepI;
            else if (t == k)     np = 32 + 2 * stepI;
            else if (t < 30)     np = sPair[t + 1];
            else                 np = DSLOT;
            g_cidx[b * L_ + t] = np;
        }
        if (t == 0) {
            int A = 31 + 2 * stepI, Bc = 32 + 2 * stepI;
            g_tasks[2 * b] = (k > 0) ? make_int4(b, sPos[k - 1], mslot, A)
                                     : make_int4(b, ZSLOT, ZSLOT, DSLOT);
            int r = (k + 2 <= 31) ? sPos[k + 2] : ZSLOT;
            g_tasks[2 * b + 1] = make_int4(b, mslot, r, Bc);
            g_newSlot[b] = mslot;
        }
    } else {
        float* nd = &nodes[(b * 63 + 32 + stepI) * H_];
        if (stepI == L_ - 2) {
            int rs = sPos[0];
            const float* ph = &g_poolH[(b * PSLOT + rs) * H_];
            const float* pc = &g_poolC[(b * PSLOT + rs) * H_];
            for (int j = t; j < H_; j += blockDim.x) {
                float hvv = ph[j];
                nd[j] = hvv; hf[b * H_ + j] = hvv; cf[b * H_ + j] = pc[j];
            }
        } else {
            int cs = sPair[0];
            const float* ch = &g_cacheH[(b * CSLOT + cs) * H_];
            for (int j = t; j < H_; j += blockDim.x) nd[j] = ch[j];
        }
        if (t == 0) {
            g_tasks[2 * b]     = make_int4(b, ZSLOT, ZSLOT, DSLOT);
            g_tasks[2 * b + 1] = make_int4(b, ZSLOT, ZSLOT, DSLOT);
            g_newSlot[b] = ZSLOT;
        }
    }
    __syncthreads();
}

// ---------------------------------------------------------------------------
// Persistent kernel: act0 (4 uniform rounds over 320 half-CTAs) -> select0 ->
// 30x [u-GEMM (80 n-tiles x 2 k-chunks, direct partial stores) | act+select].
// __launch_bounds__(256, 2): regs <= 128 -> 2 CTAs/SM -> all 160 co-resident.
// ---------------------------------------------------------------------------
__global__ void __launch_bounds__(256, 2) kPersist(const int* __restrict__ len,
                                                   const float* __restrict__ Wc,
                                                   const float* __restrict__ bc,
                                                   const float* __restrict__ q,
                                                   float* __restrict__ nodes,
                                                   float* __restrict__ hf,
                                                   float* __restrict__ cf) {
    const int cta = blockIdx.x, tid = threadIdx.x;
    __shared__ __align__(16) float As[16][36];
    __shared__ __align__(16) float Ws[16][68];
    __shared__ int sSlot[32];
    __shared__ int sPos[32], sPair[31], sK;
    __shared__ float red[8];

    // ---- phase A: step-0 activation, 4 uniform rounds (sync-safe padding)
    {
        const int hid = cta * 2 + (tid >> 7);   // 0..319
        for (int r = 0; r < 4; r++) {
            int t = r * 320 + hid;
            int b = 0, ls = ZSLOT, rs = ZSLOT, cs = DSLOT;
            if (t < B_ * (L_ - 1)) {
                int bb = t / (L_ - 1), j = t % (L_ - 1);
                if (j < len[bb] - 1) { b = bb; ls = j; rs = j + 1; cs = j; }
            }
            actPair4D(b, ls, rs, cs, bc, q, tid & 127, red + ((tid >> 7) << 2));
            __syncthreads();
        }
    }
    gridBar(60);
    if (cta < B_) doSelect(cta, 0, len, nodes, hf, cf, sPos, sPair, &sK);
    gridBar(61);

    const int ntile = cta % 80, kc = cta / 80;
    const int n0g = ntile * 64;
    const int half = (n0g >= H5_) ? 1 : 0;
    const int nn = n0g - half * H5_;
    const int kb = kc * 256;
    const int mS = tid >> 2, qS = tid & 3;     // staging (tid<128): rows 0..31
    const int mg = tid >> 4, tx = tid & 15;    // compute: 2 rows, 2 col-pairs
    const float* bPtr = Wc + (half * H_ + kb + (tid >> 4)) * H5_ + nn + (tid & 15) * 4;
    float* Uout = kc ? (half ? g_uRp : g_uLp) : (half ? g_uR : g_uL);

    for (int i = 1; i <= L_ - 2; i++) {
        if (tid < B_) sSlot[tid] = ((volatile int*)g_newSlot)[tid];
        __syncthreads();
        {   // ---- phase 1: u-GEMM partials, direct store
            const float* aPtr = (tid < 128)
                ? g_poolH + (mS * PSLOT + sSlot[mS]) * H_ + kb + qS * 4 : g_poolH;
            float4 xr, wv;
            if (tid < 128) xr = *(const float4*)aPtr;
            wv = *(const float4*)bPtr;
            u64 acc[2][2] = {};
            for (int k0 = 0; k0 < 256; k0 += 16) {
                if (tid < 128) {
                    As[qS*4+0][mS] = xr.x; As[qS*4+1][mS] = xr.y;
                    As[qS*4+2][mS] = xr.z; As[qS*4+3][mS] = xr.w;
                }
                *(float4*)&Ws[tid >> 4][(tid & 15) * 4] = wv;
                __syncthreads();
                if (k0 + 16 < 256) {
                    if (tid < 128) xr = *(const float4*)(aPtr + k0 + 16);
                    wv = *(const float4*)(bPtr + (k0 + 16) * H5_);
                }
#pragma unroll
                for (int kk = 0; kk < 16; kk++) {
                    float a0 = As[kk][mg * 2], a1 = As[kk][mg * 2 + 1];
                    u64 b01 = *(const u64*)&Ws[kk][tx*2];
                    u64 b23 = *(const u64*)&Ws[kk][32 + tx*2];
                    u64 pa0 = pk2(a0, a0), pa1 = pk2(a1, a1);
                    FFMA2(acc[0][0], pa0, b01); FFMA2(acc[0][1], pa0, b23);
                    FFMA2(acc[1][0], pa1, b01); FFMA2(acc[1][1], pa1, b23);
                }
                __syncthreads();
            }
#pragma unroll
            for (int e = 0; e < 2; e++) {
                int r = mg * 2 + e;
                float* base = Uout + (r * PSLOT + sSlot[r]) * H5_ + nn;
                *(float2*)(base + tx * 2)      = up2(acc[e][0]);
                *(float2*)(base + 32 + tx * 2) = up2(acc[e][1]);
            }
        }
        gridBar(2 * (i - 1));
        // ---- phase 2: act (2 tasks, warp halves) + select (32 CTAs)
        if (cta < B_) {
            int4 tk = (tid < 128) ? g_tasks[2 * cta] : g_tasks[2 * cta + 1];
            actPair4D(cta, tk.y, tk.z, tk.w, bc, q, tid & 127, red + ((tid >> 7) << 2));
            __syncthreads();
            doSelect(cta, i, len, nodes, hf, cf, sPos, sPair, &sK);
        }
        gridBar(2 * (i - 1) + 1);
    }
}

// ---------------------------------------------------------------------------
extern "C" void kernel_launch(void* const* d_in, const int* in_sizes, int n_in,
                              void* d_out, int out_size) {
    const float* inp = (const float*)d_in[0];
    const int*   len = (const int*)  d_in[1];
    const float* Ww  = (const float*)d_in[2];
    const float* bw  = (const float*)d_in[3];
    const float* Wc  = (const float*)d_in[4];
    const float* bc  = (const float*)d_in[5];
    const float* q   = (const float*)d_in[6];
    float* out   = (float*)d_out;
    float* hf    = out;
    float* cf    = out + B_ * H_;
    float* nodes = out + 2 * B_ * H_;

    kInit<<<64, 256>>>(len);
    kLeafGemm<<<dim3(32, 8), 128>>>(inp, Ww, bw, nodes);
    kUGemm0<<<dim3(32, 40), 128>>>(Wc);
    kPersist<<<NCTA, 256>>>(len, Wc, bc, q, nodes, hf, cf);  // <- ncu capture slot
}

// round 14
// speedup vs baseline: 1.2044x; 1.2044x over previous
#include <cuda_runtime.h>
#include <math.h>

namespace {
constexpr int B_ = 32, L_ = 32, D_ = 512, H_ = 512;
constexpr int H2_ = 1024, H5_ = 2560;
constexpr int PSLOT = 64, ZSLOT = 63;   // pool slots per batch; 63 = zero slot
constexpr int CSLOT = 96, DSLOT = 95;   // cache slots per batch; 95 = dummy
constexpr int NPART = B_ * PSLOT * H5_; // one u-buffer's element count
}

typedef unsigned long long u64;

__device__ __align__(16) float g_poolH[B_ * PSLOT * H_];
__device__ __align__(16) float g_poolC[B_ * PSLOT * H_];
__device__ __align__(16) float g_uL[NPART];
__device__ __align__(16) float g_uR[NPART];
__device__ __align__(16) float g_uLp[3 * NPART];   // k-chunk 1..3 partials (L)
__device__ __align__(16) float g_uRp[3 * NPART];   // k-chunk 1..3 partials (R)
__device__ __align__(16) float g_zero[H5_];        // zero page for leaf partials
__device__ __align__(16) float g_cacheH[B_ * CSLOT * H_];
__device__ __align__(16) float g_cacheC[B_ * CSLOT * H_];
__device__ float g_logit[B_ * CSLOT];
__device__ int4  g_tasks[2 * B_];
__device__ int   g_newSlot[B_];
__device__ int   g_slotOf[B_ * L_];
__device__ int   g_cidx[B_ * L_];
__device__ int2  g_mlist[1024];
__device__ int   g_mcount;

__device__ __forceinline__ float sigm(float x) { return 1.f / (1.f + expf(-x)); }

#define FFMA2(d, a, b) asm("fma.rn.f32x2 %0, %1, %2, %0;" : "+l"(d) : "l"(a), "l"(b))
__device__ __forceinline__ u64 pk2(float lo, float hi) {
    u64 r; asm("mov.b64 %0, {%1, %2};" : "=l"(r) : "f"(lo), "f"(hi)); return r;
}
__device__ __forceinline__ float2 up2(u64 p) {
    float2 r; asm("mov.b64 {%0, %1}, %2;" : "=f"(r.x), "=f"(r.y) : "l"(p)); return r;
}

// ---------------------------------------------------------------------------
__global__ void kInit(const int* __restrict__ len) {
    int t = blockIdx.x * blockDim.x + threadIdx.x;
    int nthr = gridDim.x * blockDim.x;   // 16384
    if (t < B_ * L_) {
        int p = t % L_;
        g_slotOf[t] = p;
        g_cidx[t]   = (p < L_ - 1) ? p : DSLOT;
    }
    if (t < B_) g_logit[t * CSLOT + DSLOT] = 0.f;
    if (t < H5_) g_zero[t] = 0.f;
    if (blockIdx.x == 0 && threadIdx.x < B_) {
        int b = threadIdx.x, off = 0;
        for (int j = 0; j < b; j++) {
            int c = len[j] + 1; if (c > 32) c = 32; off += c;
        }
        int c = len[b] + 1; if (c > 32) c = 32;
        for (int j = 0; j < c; j++) g_mlist[off + j] = make_int2(b, j);
        if (b == B_ - 1) g_mcount = off + c;
    }
    for (int i = t; i < B_ * H_; i += nthr) {
        int b = i / H_, j = i % H_;
        g_poolH[(b * PSLOT + ZSLOT) * H_ + j] = 0.f;
        g_poolC[(b * PSLOT + ZSLOT) * H_ + j] = 0.f;
        g_cacheH[(b * CSLOT + DSLOT) * H_ + j] = 0.f;
        g_cacheC[(b * CSLOT + DSLOT) * H_ + j] = 0.f;
    }
    for (int i = t; i < B_ * H5_; i += nthr) {
        int b = i / H5_, j = i % H5_;
        g_uL[(b * PSLOT + ZSLOT) * H5_ + j] = 0.f;
        g_uR[(b * PSLOT + ZSLOT) * H5_ + j] = 0.f;
    }
}

// ---------------------------------------------------------------------------
// 32x128 GEMM core, 128 threads, 4 rows x 8 cols per thread (f32x2 packed).
// ---------------------------------------------------------------------------
__device__ __forceinline__ void gemm32core(const float* aPtr, const float* bPtr,
                                           int ldb, int K, int tid,
                                           float (*Xs)[44], float (*Ws)[132],
                                           u64 (*acc)[4]) {
    const int ar = tid >> 2, aq = (tid & 3) * 4;
    const int wr = tid >> 3, wj = tid & 7;
    const int ty = tid >> 4, tx = tid & 15;
    float4 xa  = *(const float4*)(aPtr);
    float4 wv0 = *(const float4*)(bPtr);
    float4 wv1 = *(const float4*)(bPtr + 32);
    float4 wv2 = *(const float4*)(bPtr + 64);
    float4 wv3 = *(const float4*)(bPtr + 96);
    for (int k0 = 0; k0 < K; k0 += 16) {
        Xs[aq+0][ar] = xa.x; Xs[aq+1][ar] = xa.y;
        Xs[aq+2][ar] = xa.z; Xs[aq+3][ar] = xa.w;
        *(float4*)&Ws[wr][wj*4     ] = wv0;
        *(float4*)&Ws[wr][wj*4 + 32] = wv1;
        *(float4*)&Ws[wr][wj*4 + 64] = wv2;
        *(float4*)&Ws[wr][wj*4 + 96] = wv3;
        __syncthreads();
        if (k0 + 16 < K) {
            xa = *(const float4*)(aPtr + k0 + 16);
            const float* bn = bPtr + (k0 + 16) * ldb;
            wv0 = *(const float4*)(bn);
            wv1 = *(const float4*)(bn + 32);
            wv2 = *(const float4*)(bn + 64);
            wv3 = *(const float4*)(bn + 96);
        }
#pragma unroll
        for (int kk = 0; kk < 16; kk++) {
            float4 a = *(const float4*)&Xs[kk][ty*4];
            u64 pa0 = pk2(a.x,a.x), pa1 = pk2(a.y,a.y);
            u64 pa2 = pk2(a.z,a.z), pa3 = pk2(a.w,a.w);
            u64 bb0 = *(const u64*)&Ws[kk][tx*2];
            u64 bb1 = *(const u64*)&Ws[kk][32 + tx*2];
            u64 bb2 = *(const u64*)&Ws[kk][64 + tx*2];
            u64 bb3 = *(const u64*)&Ws[kk][96 + tx*2];
            FFMA2(acc[0][0],pa0,bb0); FFMA2(acc[0][1],pa0,bb1); FFMA2(acc[0][2],pa0,bb2); FFMA2(acc[0][3],pa0,bb3);
            FFMA2(acc[1][0],pa1,bb0); FFMA2(acc[1][1],pa1,bb1); FFMA2(acc[1][2],pa1,bb2); FFMA2(acc[1][3],pa1,bb3);
            FFMA2(acc[2][0],pa2,bb0); FFMA2(acc[2][1],pa2,bb1); FFMA2(acc[2][2],pa2,bb2); FFMA2(acc[2][3],pa2,bb3);
            FFMA2(acc[3][0],pa3,bb0); FFMA2(acc[3][1],pa3,bb1); FFMA2(acc[3][2],pa3,bb2); FFMA2(acc[3][3],pa3,bb3);
        }
        __syncthreads();
    }
}

// ---------------------------------------------------------------------------
// Leaf GEMM: hc = inp @ W_word + b_word. M=1024, N=1024, K=512. grid(32,8).
// ---------------------------------------------------------------------------
__global__ void __launch_bounds__(128) kLeafGemm(const float* __restrict__ inp,
                                                 const float* __restrict__ Ww,
                                                 const float* __restrict__ bw,
                                                 float* __restrict__ nodes) {
    const int m0 = blockIdx.x * 32, n0 = blockIdx.y * 128;
    __shared__ __align__(16) float Xs[16][44];
    __shared__ __align__(16) float Ws[16][132];
    const int tid = threadIdx.x;
    u64 acc[4][4] = {};
    const float* aPtr = inp + (m0 + (tid >> 2)) * D_ + (tid & 3) * 4;
    const float* bPtr = Ww + (tid >> 3) * H2_ + n0 + (tid & 7) * 4;
    gemm32core(aPtr, bPtr, H2_, D_, tid, Xs, Ws, acc);

    const int ty = tid >> 4, tx = tid & 15;
    const int cHalf = (n0 >= H_) ? 1 : 0;
#pragma unroll
    for (int r = 0; r < 4; r++) {
        int m = m0 + ty * 4 + r, b = m / L_, l = m % L_;
#pragma unroll
        for (int p = 0; p < 4; p++) {
            int n = n0 + 32 * p + tx * 2;
            float2 bias = *(const float2*)(bw + n);
            float2 v = up2(acc[r][p]);
            v.x += bias.x; v.y += bias.y;
            if (!cHalf) {
                *(float2*)&g_poolH[(b * PSLOT + l) * H_ + n] = v;
                *(float2*)&nodes[(b * 63 + l) * H_ + n] = v;
            } else {
                *(float2*)&g_poolC[(b * PSLOT + l) * H_ + (n - H_)] = v;
            }
        }
    }
}

// ---------------------------------------------------------------------------
// Compacted front u-GEMM, both halves: grid(32, 40); y<20 -> uL, else uR.
// ---------------------------------------------------------------------------
__global__ void __launch_bounds__(128) kUGemm0(const float* __restrict__ Wc) {
    const int cnt = g_mcount;
    const int m0 = blockIdx.x * 32;
    if (m0 >= cnt) return;
    const int half = (blockIdx.y >= 20) ? 1 : 0;
    const int nn = (blockIdx.y - half * 20) * 128;
    __shared__ __align__(16) float Xs[16][44];
    __shared__ __align__(16) float Ws[16][132];
    __shared__ int2 sRows[32];
    const int tid = threadIdx.x;
    if (tid < 32) {
        int r = m0 + tid; if (r >= cnt) r = cnt - 1;
        sRows[tid] = g_mlist[r];
    }
    __syncthreads();
    u64 acc[4][4] = {};
    int2 me = sRows[tid >> 2];
    const float* aPtr = g_poolH + (me.x * PSLOT + me.y) * H_ + (tid & 3) * 4;
    const float* bPtr = Wc + (half * H_ + (tid >> 3)) * H5_ + nn + (tid & 7) * 4;
    gemm32core(aPtr, bPtr, H5_, H_, tid, Xs, Ws, acc);

    const int ty = tid >> 4, tx = tid & 15;
    float* U = half ? g_uR : g_uL;
#pragma unroll
    for (int r = 0; r < 4; r++) {
        int row = m0 + ty * 4 + r;
        if (row < cnt) {
            int2 e = sRows[ty * 4 + r];
            float* dst = U + (e.x * PSLOT + e.y) * H5_ + nn;
#pragma unroll
            for (int p = 0; p < 4; p++)
                *(float2*)&dst[32 * p + tx * 2] = up2(acc[r][p]);
        }
    }
}

// ---------------------------------------------------------------------------
// Per-step u-GEMM: grid (80 n-tiles, 4 k-chunks), 256 thr, K=128 per chunk.
// Chunk 0 -> primary uL/uR; chunks 1..3 -> private partial buffers.
// Direct stores, no atomics, no zeroing.
// ---------------------------------------------------------------------------
__global__ void __launch_bounds__(256) kGemmStep(const float* __restrict__ Wc) {
    const int n0g = blockIdx.x * 64;
    const int half = (n0g >= H5_) ? 1 : 0;
    const int nn = n0g - half * H5_;
    const int kc = blockIdx.y;           // 0..3
    const int kb = kc * 128;
    __shared__ __align__(16) float As[16][36];
    __shared__ __align__(16) float Ws[16][68];
    __shared__ int sSlot[32];
    const int tid = threadIdx.x;
    if (tid < B_) sSlot[tid] = g_newSlot[tid];
    __syncthreads();

    const int mS = tid >> 2, qS = tid & 3;     // staging (tid<128): rows 0..31
    const int mg = tid >> 4, tx = tid & 15;    // compute: 2 rows, 2 col-pairs
    const float* aPtr = (tid < 128)
        ? g_poolH + (mS * PSLOT + sSlot[mS]) * H_ + kb + qS * 4 : g_poolH;
    const float* bPtr = Wc + (half * H_ + kb + (tid >> 4)) * H5_ + nn + (tid & 15) * 4;
    float4 xr, wv;
    if (tid < 128) xr = *(const float4*)aPtr;
    wv = *(const float4*)bPtr;
    u64 acc[2][2] = {};
    for (int k0 = 0; k0 < 128; k0 += 16) {
        if (tid < 128) {
            As[qS*4+0][mS] = xr.x; As[qS*4+1][mS] = xr.y;
            As[qS*4+2][mS] = xr.z; As[qS*4+3][mS] = xr.w;
        }
        *(float4*)&Ws[tid >> 4][(tid & 15) * 4] = wv;
        __syncthreads();
        if (k0 + 16 < 128) {
            if (tid < 128) xr = *(const float4*)(aPtr + k0 + 16);
            wv = *(const float4*)(bPtr + (k0 + 16) * H5_);
        }
#pragma unroll
        for (int kk = 0; kk < 16; kk++) {
            float a0 = As[kk][mg * 2], a1 = As[kk][mg * 2 + 1];
            u64 b01 = *(const u64*)&Ws[kk][tx*2];
            u64 b23 = *(const u64*)&Ws[kk][32 + tx*2];
            u64 pa0 = pk2(a0, a0), pa1 = pk2(a1, a1);
            FFMA2(acc[0][0], pa0, b01); FFMA2(acc[0][1], pa0, b23);
            FFMA2(acc[1][0], pa1, b01); FFMA2(acc[1][1], pa1, b23);
        }
        __syncthreads();
    }
    float* Uout = (kc == 0) ? (half ? g_uR : g_uL)
                            : ((half ? g_uRp : g_uLp) + (kc - 1) * NPART);
#pragma unroll
    for (int e = 0; e < 2; e++) {
        int r = mg * 2 + e;
        float* base = Uout + (r * PSLOT + sSlot[r]) * H5_ + nn;
        *(float2*)(base + tx * 2)      = up2(acc[e][0]);
        *(float2*)(base + 32 + tx * 2) = up2(acc[e][1]);
    }
}

// ---------------------------------------------------------------------------
// 4-partial pair activation: u = ((u0+p1)+(p2+p3)); leaf slots (<32) read the
// zero page for partials. lt in [0,128), each thread does 4 elements.
// ---------------------------------------------------------------------------
__device__ __forceinline__ void actPair4D(int b, int ls, int rs, int cs,
                                          const float* __restrict__ bc,
                                          const float* __restrict__ q,
                                          int lt, float* red) {
    const float* ul = g_uL + (b * PSLOT + ls) * H5_;
    const float* ur = g_uR + (b * PSLOT + rs) * H5_;
    const float *lp1, *lp2, *lp3, *rp1, *rp2, *rp3;
    if (ls < 32) { lp1 = lp2 = lp3 = g_zero; }
    else {
        int o = (b * PSLOT + ls) * H5_;
        lp1 = g_uLp + o; lp2 = g_uLp + NPART + o; lp3 = g_uLp + 2 * NPART + o;
    }
    if (rs < 32) { rp1 = rp2 = rp3 = g_zero; }
    else {
        int o = (b * PSLOT + rs) * H5_;
        rp1 = g_uRp + o; rp2 = g_uRp + NPART + o; rp3 = g_uRp + 2 * NPART + o;
    }
    const float* cl = g_poolC + (b * PSLOT + ls) * H_;
    const float* cr = g_poolC + (b * PSLOT + rs) * H_;
    float* oh = g_cacheH + (b * CSLOT + cs) * H_;
    float* oc = g_cacheC + (b * CSLOT + cs) * H_;
    int j = lt * 4;
    float G[5][4];
#pragma unroll
    for (int g = 0; g < 5; g++) {
        int o = g * H_ + j;
        float4 a  = *(const float4*)(ul + o);
        float4 a1 = *(const float4*)(lp1 + o);
        float4 a2 = *(const float4*)(lp2 + o);
        float4 a3 = *(const float4*)(lp3 + o);
        float4 r  = *(const float4*)(ur + o);
        float4 r1 = *(const float4*)(rp1 + o);
        float4 r2 = *(const float4*)(rp2 + o);
        float4 r3 = *(const float4*)(rp3 + o);
        float4 c  = *(const float4*)(bc + o);
        G[g][0] = ((a.x + a1.x) + (a2.x + a3.x)) + ((r.x + r1.x) + (r2.x + r3.x)) + c.x;
        G[g][1] = ((a.y + a1.y) + (a2.y + a3.y)) + ((r.y + r1.y) + (r2.y + r3.y)) + c.y;
        G[g][2] = ((a.z + a1.z) + (a2.z + a3.z)) + ((r.z + r1.z) + (r2.z + r3.z)) + c.z;
        G[g][3] = ((a.w + a1.w) + (a2.w + a3.w)) + ((r.w + r1.w) + (r2.w + r3.w)) + c.w;
    }
    float4 cl4 = *(const float4*)(cl + j);
    float4 cr4 = *(const float4*)(cr + j);
    float4 q4  = *(const float4*)(q + j);
    float clv[4] = {cl4.x, cl4.y, cl4.z, cl4.w};
    float crv[4] = {cr4.x, cr4.y, cr4.z, cr4.w};
    float hv[4], cv[4];
#pragma unroll
    for (int l = 0; l < 4; l++) {
        float c = clv[l] * sigm(G[1][l] + 1.f) + crv[l] * sigm(G[2][l] + 1.f)
                + tanhf(G[3][l]) * sigm(G[0][l]);
        hv[l] = sigm(G[4][l]) * tanhf(c); cv[l] = c;
    }
    *(float4*)(oh + j) = make_float4(hv[0], hv[1], hv[2], hv[3]);
    *(float4*)(oc + j) = make_float4(cv[0], cv[1], cv[2], cv[3]);
    float acc = hv[0]*q4.x + hv[1]*q4.y + hv[2]*q4.z + hv[3]*q4.w;
    for (int o = 16; o > 0; o >>= 1) acc += __shfl_down_sync(0xffffffffu, acc, o);
    if ((lt & 31) == 0) red[lt >> 5] = acc;
    __syncthreads();
    if (lt == 0)
        g_logit[b * CSLOT + cs] = red[0] + red[1] + red[2] + red[3];
}

__global__ void __launch_bounds__(128) kAct0(const int* __restrict__ len,
                                             const float* __restrict__ bc,
                                             const float* __restrict__ q) {
    __shared__ float red[4];
    int b = blockIdx.y, j = blockIdx.x;
    if (j >= len[b] - 1) return;
    actPair4D(b, j, j + 1, j, bc, q, threadIdx.x, red);
}

// ---------------------------------------------------------------------------
// Select for batch b at step stepI (direct-store partials: no zeroing).
// ---------------------------------------------------------------------------
__device__ void doSelect(int b, int stepI, const int* __restrict__ len,
                         float* __restrict__ nodes, float* __restrict__ hf,
                         float* __restrict__ cf,
                         int* sPos, int* sPair, int* sKp) {
    int t = threadIdx.x;
    if (t < 32) sPos[t] = g_slotOf[b * L_ + t];
    if (t < 31) sPair[t] = g_cidx[b * L_ + t];
    __syncthreads();
    int lb = len[b];
    if (stepI < lb - 1) {
        if (t == 0) {
            int cand = lb - 1 - stepI, k = 0;
            float best = -1e30f;
            for (int j = 0; j < cand; j++) {
                float v = g_logit[b * CSLOT + sPair[j]];
                if (v > best) { best = v; k = j; }
            }
            *sKp = k;
        }
        __syncthreads();
        int k = *sKp, cs = sPair[k], mslot = 32 + stepI;
        const float* ch = &g_cacheH[(b * CSLOT + cs) * H_];
        const float* cc = &g_cacheC[(b * CSLOT + cs) * H_];
        float* ph = &g_poolH[(b * PSLOT + mslot) * H_];
        float* pc = &g_poolC[(b * PSLOT + mslot) * H_];
        float* nd = &nodes[(b * 63 + 32 + stepI) * H_];
        for (int j = t; j < H_; j += blockDim.x) {
            float hvv = ch[j], cvv = cc[j];
            ph[j] = hvv; pc[j] = cvv; nd[j] = hvv;
            if (stepI == L_ - 2) { hf[b * H_ + j] = hvv; cf[b * H_ + j] = cvv; }
        }
        if (t < 32) {
            int np = (t < k) ? sPos[t] : (t == k) ? mslot : (t < 31) ? sPos[t + 1] : ZSLOT;
            g_slotOf[b * L_ + t] = np;
        }
        if (t < 31) {
            int np;
            if      (t <  k - 1) np = sPair[t];
            else if (t == k - 1) np = 31 + 2 * stepI;
            else if (t == k)     np = 32 + 2 * stepI;
            else if (t < 30)     np = sPair[t + 1];
            else                 np = DSLOT;
            g_cidx[b * L_ + t] = np;
        }
        if (t == 0) {
            int A = 31 + 2 * stepI, Bc = 32 + 2 * stepI;
            g_tasks[2 * b] = (k > 0) ? make_int4(b, sPos[k - 1], mslot, A)
                                     : make_int4(b, ZSLOT, ZSLOT, DSLOT);
            int r = (k + 2 <= 31) ? sPos[k + 2] : ZSLOT;
            g_tasks[2 * b + 1] = make_int4(b, mslot, r, Bc);
            g_newSlot[b] = mslot;
        }
    } else {
        float* nd = &nodes[(b * 63 + 32 + stepI) * H_];
        if (stepI == L_ - 2) {
            int rs = sPos[0];
            const float* ph = &g_poolH[(b * PSLOT + rs) * H_];
            const float* pc = &g_poolC[(b * PSLOT + rs) * H_];
            for (int j = t; j < H_; j += blockDim.x) {
                float hvv = ph[j];
                nd[j] = hvv; hf[b * H_ + j] = hvv; cf[b * H_ + j] = pc[j];
            }
        } else {
            int cs = sPair[0];
            const float* ch = &g_cacheH[(b * CSLOT + cs) * H_];
            for (int j = t; j < H_; j += blockDim.x) nd[j] = ch[j];
        }
        if (t == 0) {
            g_tasks[2 * b]     = make_int4(b, ZSLOT, ZSLOT, DSLOT);
            g_tasks[2 * b + 1] = make_int4(b, ZSLOT, ZSLOT, DSLOT);
            g_newSlot[b] = ZSLOT;
        }
    }
    __syncthreads();
}

// ---------------------------------------------------------------------------
__global__ void __launch_bounds__(256) kSel0(const int* __restrict__ len,
                                             float* __restrict__ nodes,
                                             float* __restrict__ hf,
                                             float* __restrict__ cf) {
    __shared__ int sPos[32], sPair[31], sK;
    doSelect(blockIdx.x, 0, len, nodes, hf, cf, sPos, sPair, &sK);
}

// ---------------------------------------------------------------------------
// Fused act (2 tasks in warp-halves) + select. One CTA per batch.
// ---------------------------------------------------------------------------
__global__ void __launch_bounds__(256) kActSel(const int* __restrict__ len,
                                               const float* __restrict__ bc,
                                               const float* __restrict__ q,
                                               float* __restrict__ nodes,
                                               float* __restrict__ hf,
                                               float* __restrict__ cf,
                                               int stepI) {
    __shared__ int sPos[32], sPair[31], sK;
    __shared__ float red[8];
    int b = blockIdx.x, tid = threadIdx.x;
    int4 tk = (tid < 128) ? g_tasks[2 * b] : g_tasks[2 * b + 1];
    actPair4D(b, tk.y, tk.z, tk.w, bc, q, tid & 127, red + ((tid >> 7) << 2));
    __syncthreads();
    doSelect(b, stepI, len, nodes, hf, cf, sPos, sPair, &sK);
}

// ---------------------------------------------------------------------------
extern "C" void kernel_launch(void* const* d_in, const int* in_sizes, int n_in,
                              void* d_out, int out_size) {
    const float* inp = (const float*)d_in[0];
    const int*   len = (const int*)  d_in[1];
    const float* Ww  = (const float*)d_in[2];
    const float* bw  = (const float*)d_in[3];
    const float* Wc  = (const float*)d_in[4];
    const float* bc  = (const float*)d_in[5];
    const float* q   = (const float*)d_in[6];
    float* out   = (float*)d_out;
    float* hf    = out;
    float* cf    = out + B_ * H_;
    float* nodes = out + 2 * B_ * H_;

    kInit<<<64, 256>>>(len);
    kLeafGemm<<<dim3(32, 8), 128>>>(inp, Ww, bw, nodes);
    kUGemm0<<<dim3(32, 40), 128>>>(Wc);
    kAct0<<<dim3(31, B_), 128>>>(len, bc, q);
    kSel0<<<B_, 256>>>(len, nodes, hf, cf);
    for (int i = 1; i <= L_ - 2; i++) {
        kGemmStep<<<dim3(80, 4), 256>>>(Wc);
        kActSel<<<B_, 256>>>(len, bc, q, nodes, hf, cf, i);
    }
}